// round 2
// baseline (speedup 1.0000x reference)
#include <cuda_runtime.h>
#include <cuda_bf16.h>

#define N_NODES 50000
#define N_EDGES 600000
#define LATENT 128
#define IN_FEAT 7
#define STEPS 3

// -------- scratch (static device globals; no allocation) --------
__device__ float g_h [N_NODES * LATENT];
__device__ float g_x1[N_NODES * LATENT];
__device__ float g_x2[N_NODES * LATENT];
__device__ float g_deg_s[N_NODES];
__device__ float g_inv_s[N_NODES];
__device__ int   g_cnt_r[N_NODES];
__device__ int   g_off  [N_NODES + 1];
__device__ int   g_cursor[N_NODES];
__device__ int   g_esrc [N_EDGES];
__device__ int   g_incl [50176];
__device__ int   g_bsum [64];
__device__ int   g_boff [64];

__device__ __forceinline__ float* selbuf(int s) {
    return (s == 0) ? g_h : (s == 1) ? g_x1 : g_x2;
}

// ---------------- degree / CSR build ----------------
__global__ void k_zero() {
    int i = blockIdx.x * blockDim.x + threadIdx.x;
    if (i < N_NODES) { g_deg_s[i] = 0.f; g_cnt_r[i] = 0; }
}

__global__ void k_count(const int* __restrict__ snd, const int* __restrict__ rcv) {
    int e = blockIdx.x * blockDim.x + threadIdx.x;
    if (e < N_EDGES) {
        atomicAdd(&g_deg_s[snd[e]], 1.0f);
        atomicAdd(&g_cnt_r[rcv[e]], 1);
    }
}

__global__ void k_scan1() {
    int i = blockIdx.x * 1024 + threadIdx.x;
    int v = (i < N_NODES) ? g_cnt_r[i] : 0;
    int x = v;
    #pragma unroll
    for (int d = 1; d < 32; d <<= 1) {
        int y = __shfl_up_sync(0xFFFFFFFFu, x, d);
        if ((threadIdx.x & 31) >= d) x += y;
    }
    __shared__ int wsum[32];
    if ((threadIdx.x & 31) == 31) wsum[threadIdx.x >> 5] = x;
    __syncthreads();
    if (threadIdx.x < 32) {
        int y = wsum[threadIdx.x];
        #pragma unroll
        for (int d = 1; d < 32; d <<= 1) {
            int z = __shfl_up_sync(0xFFFFFFFFu, y, d);
            if (threadIdx.x >= d) y += z;
        }
        wsum[threadIdx.x] = y;
    }
    __syncthreads();
    if (threadIdx.x >= 32) x += wsum[(threadIdx.x >> 5) - 1];
    g_incl[i] = x;
    if (threadIdx.x == 1023) g_bsum[blockIdx.x] = x;
}

__global__ void k_scan2(int nblocks) {
    if (threadIdx.x == 0 && blockIdx.x == 0) {
        int run = 0;
        for (int i = 0; i < nblocks; i++) { g_boff[i] = run; run += g_bsum[i]; }
    }
}

// scan finalize + inv_sqrt_s fused
__global__ void k_scan3() {
    int i = blockIdx.x * 1024 + threadIdx.x;
    if (i < N_NODES) {
        int v = g_cnt_r[i];
        int e = g_boff[blockIdx.x] + g_incl[i] - v;
        g_off[i] = e;
        g_cursor[i] = e;
        g_inv_s[i] = rsqrtf(fmaxf(g_deg_s[i], 1.0f));
    }
    if (i == 0) g_off[N_NODES] = N_EDGES;
}

__global__ void k_fill(const int* __restrict__ snd, const int* __restrict__ rcv) {
    int e = blockIdx.x * blockDim.x + threadIdx.x;
    if (e < N_EDGES) {
        int r = rcv[e];
        int pos = atomicAdd(&g_cursor[r], 1);
        g_esrc[pos] = snd[e];
    }
}

// ---------------- embed ----------------
__global__ void k_embed(const float* __restrict__ nodes,
                        const float* __restrict__ Wemb,
                        const float* __restrict__ bemb) {
    int idx = blockIdx.x * blockDim.x + threadIdx.x;
    if (idx >= N_NODES * LATENT) return;
    int n = idx >> 7;
    int c = idx & 127;
    float acc = bemb[c];
    #pragma unroll
    for (int k = 0; k < IN_FEAT; k++)
        acc = fmaf(nodes[n * IN_FEAT + k], Wemb[k * LATENT + c], acc);
    g_h[idx] = acc;
}

// ---------------- GEMM: C[M,128] = act(A[M,128] @ W[128,128] + b) * rowscale ----------------
// BM=128, BN=128, BK=8, 256 threads, TM=8, TN=8, double-buffered smem, reg prefetch
__global__ __launch_bounds__(256, 2) void k_gemm(int srcSel, int dstSel,
                                                 const float* __restrict__ W,
                                                 const float* __restrict__ bias,
                                                 int doRelu, int useInvS) {
    const float* __restrict__ A = selbuf(srcSel);
    float* __restrict__ C = selbuf(dstSel);

    __shared__ float As[2][8][128];   // [k][row] transposed
    __shared__ float Bs[2][8][128];   // [k][col]

    const int tid = threadIdx.x;
    const int rowBase = blockIdx.x * 128;

    // load mapping
    const int arow = tid >> 1;            // 0..127
    const int acol = (tid & 1) * 4;       // 0 or 4 (k offset)
    const int brow = tid >> 5;            // 0..7
    const int bcol = (tid & 31) * 4;      // 0..124

    // compute mapping
    const int ty = tid >> 4;              // 0..15 -> rows ty*8..
    const int tx = tid & 15;              // 0..15 -> cols tx*8..

    const bool arowOK = (rowBase + arow) < N_NODES;
    const float* Aptr = A + (size_t)(rowBase + arow) * 128 + acol;
    const float* Bptr = W + brow * 128 + bcol;

    // prologue: tile 0 -> buf 0
    {
        float4 av = arowOK ? *(const float4*)Aptr : make_float4(0.f, 0.f, 0.f, 0.f);
        float4 bv = *(const float4*)Bptr;
        As[0][acol + 0][arow] = av.x;
        As[0][acol + 1][arow] = av.y;
        As[0][acol + 2][arow] = av.z;
        As[0][acol + 3][arow] = av.w;
        *(float4*)&Bs[0][brow][bcol] = bv;
    }
    __syncthreads();

    float acc[8][8];
    #pragma unroll
    for (int i = 0; i < 8; i++)
        #pragma unroll
        for (int j = 0; j < 8; j++) acc[i][j] = 0.f;

    #pragma unroll
    for (int t = 0; t < 16; t++) {
        const int buf = t & 1;
        float4 an, bn;
        if (t < 15) {
            an = arowOK ? *(const float4*)(Aptr + (t + 1) * 8)
                        : make_float4(0.f, 0.f, 0.f, 0.f);
            bn = *(const float4*)(Bptr + (t + 1) * 8 * 128);
        }
        #pragma unroll
        for (int k = 0; k < 8; k++) {
            float a[8], b[8];
            *(float4*)&a[0] = *(const float4*)&As[buf][k][ty * 8];
            *(float4*)&a[4] = *(const float4*)&As[buf][k][ty * 8 + 4];
            *(float4*)&b[0] = *(const float4*)&Bs[buf][k][tx * 8];
            *(float4*)&b[4] = *(const float4*)&Bs[buf][k][tx * 8 + 4];
            #pragma unroll
            for (int i = 0; i < 8; i++)
                #pragma unroll
                for (int j = 0; j < 8; j++)
                    acc[i][j] = fmaf(a[i], b[j], acc[i][j]);
        }
        if (t < 15) {
            const int nxt = buf ^ 1;
            As[nxt][acol + 0][arow] = an.x;
            As[nxt][acol + 1][arow] = an.y;
            As[nxt][acol + 2][arow] = an.z;
            As[nxt][acol + 3][arow] = an.w;
            *(float4*)&Bs[nxt][brow][bcol] = bn;
            __syncthreads();
        }
    }

    float bv0[8];
    *(float4*)&bv0[0] = *(const float4*)&bias[tx * 8];
    *(float4*)&bv0[4] = *(const float4*)&bias[tx * 8 + 4];

    #pragma unroll
    for (int i = 0; i < 8; i++) {
        int row = rowBase + ty * 8 + i;
        if (row >= N_NODES) break;
        float o[8];
        #pragma unroll
        for (int j = 0; j < 8; j++) o[j] = acc[i][j] + bv0[j];
        if (doRelu) {
            #pragma unroll
            for (int j = 0; j < 8; j++) o[j] = fmaxf(o[j], 0.f);
        }
        if (useInvS) {
            float rs = g_inv_s[row];
            #pragma unroll
            for (int j = 0; j < 8; j++) o[j] *= rs;
        }
        *(float4*)&C[row * 128 + tx * 8]     = *(float4*)&o[0];
        *(float4*)&C[row * 128 + tx * 8 + 4] = *(float4*)&o[4];
    }
}

// ---------------- fused aggregate + skip + LayerNorm ----------------
__global__ __launch_bounds__(256) void k_agg_ln(const float* __restrict__ ln_scale,
                                                const float* __restrict__ ln_bias) {
    int node = blockIdx.x * 8 + (threadIdx.x >> 5);
    if (node >= N_NODES) return;
    int lane = threadIdx.x & 31;

    float4 acc = make_float4(0.f, 0.f, 0.f, 0.f);
    int b0 = g_off[node], b1 = g_off[node + 1];
    for (int j = b0; j < b1; j++) {
        int s = g_esrc[j];
        float4 v = *(const float4*)&g_x2[s * 128 + lane * 4];
        acc.x += v.x; acc.y += v.y; acc.z += v.z; acc.w += v.w;
    }
    float invr = rsqrtf(fmaxf((float)(b1 - b0), 1.0f));
    float4 hv = *(const float4*)&g_h[node * 128 + lane * 4];
    float4 u;
    u.x = fmaf(acc.x, invr, hv.x);
    u.y = fmaf(acc.y, invr, hv.y);
    u.z = fmaf(acc.z, invr, hv.z);
    u.w = fmaf(acc.w, invr, hv.w);

    float sum = u.x + u.y + u.z + u.w;
    float sq  = u.x * u.x + u.y * u.y + u.z * u.z + u.w * u.w;
    #pragma unroll
    for (int d = 16; d > 0; d >>= 1) {
        sum += __shfl_xor_sync(0xFFFFFFFFu, sum, d);
        sq  += __shfl_xor_sync(0xFFFFFFFFu, sq, d);
    }
    float mean = sum * (1.0f / 128.0f);
    float var = sq * (1.0f / 128.0f) - mean * mean;
    float rstd = rsqrtf(var + 1e-6f);

    float4 sc = *(const float4*)&ln_scale[lane * 4];
    float4 bi = *(const float4*)&ln_bias[lane * 4];
    float4 o;
    o.x = (u.x - mean) * rstd * sc.x + bi.x;
    o.y = (u.y - mean) * rstd * sc.y + bi.y;
    o.z = (u.z - mean) * rstd * sc.z + bi.z;
    o.w = (u.w - mean) * rstd * sc.w + bi.w;
    *(float4*)&g_h[node * 128 + lane * 4] = o;
}

// ---------------- decoder: warp per node, coalesced + shuffle reduce ----------------
__global__ __launch_bounds__(256) void k_decode(const float* __restrict__ Wdec,
                                                const float* __restrict__ bdec,
                                                float* __restrict__ out) {
    int node = blockIdx.x * 8 + (threadIdx.x >> 5);
    if (node >= N_NODES) return;
    int lane = threadIdx.x & 31;

    float4 hv = *(const float4*)&g_h[node * 128 + lane * 4];
    #pragma unroll
    for (int j = 0; j < IN_FEAT; j++) {
        float p = hv.x * __ldg(&Wdec[(lane * 4 + 0) * IN_FEAT + j])
                + hv.y * __ldg(&Wdec[(lane * 4 + 1) * IN_FEAT + j])
                + hv.z * __ldg(&Wdec[(lane * 4 + 2) * IN_FEAT + j])
                + hv.w * __ldg(&Wdec[(lane * 4 + 3) * IN_FEAT + j]);
        #pragma unroll
        for (int d = 16; d > 0; d >>= 1)
            p += __shfl_xor_sync(0xFFFFFFFFu, p, d);
        if (lane == j) out[node * IN_FEAT + j] = p + bdec[j];
    }
}

extern "C" void kernel_launch(void* const* d_in, const int* in_sizes, int n_in,
                              void* d_out, int out_size) {
    const float* nodes    = (const float*)d_in[0];
    const int*   senders  = (const int*)  d_in[1];
    const int*   receivers= (const int*)  d_in[2];
    const float* W_embed  = (const float*)d_in[3];
    const float* b_embed  = (const float*)d_in[4];
    const float* mlp_W    = (const float*)d_in[5];
    const float* mlp_b    = (const float*)d_in[6];
    const float* ln_scale = (const float*)d_in[7];
    const float* ln_bias  = (const float*)d_in[8];
    const float* W_dec    = (const float*)d_in[9];
    const float* b_dec    = (const float*)d_in[10];
    float* out = (float*)d_out;

    const int SCAN_BLOCKS = (N_NODES + 1023) / 1024;

    k_zero <<<(N_NODES + 255) / 256, 256>>>();
    k_count<<<(N_EDGES + 255) / 256, 256>>>(senders, receivers);
    k_scan1<<<SCAN_BLOCKS, 1024>>>();
    k_scan2<<<1, 32>>>(SCAN_BLOCKS);
    k_scan3<<<SCAN_BLOCKS, 1024>>>();
    k_fill <<<(N_EDGES + 255) / 256, 256>>>(senders, receivers);

    k_embed<<<(N_NODES * LATENT + 255) / 256, 256>>>(nodes, W_embed, b_embed);

    const int GEMM_GRID = (N_NODES + 127) / 128;
    for (int step = 0; step < STEPS; step++) {
        const float* W0 = mlp_W + (size_t)(step * 2 + 0) * LATENT * LATENT;
        const float* W1 = mlp_W + (size_t)(step * 2 + 1) * LATENT * LATENT;
        const float* b0 = mlp_b + (size_t)(step * 2 + 0) * LATENT;
        const float* b1 = mlp_b + (size_t)(step * 2 + 1) * LATENT;
        k_gemm<<<GEMM_GRID, 256>>>(0, 1, W0, b0, 1, 0);
        k_gemm<<<GEMM_GRID, 256>>>(1, 2, W1, b1, 1, 1);
        k_agg_ln<<<(N_NODES + 7) / 8, 256>>>(ln_scale + step * LATENT,
                                             ln_bias + step * LATENT);
    }

    k_decode<<<(N_NODES + 7) / 8, 256>>>(W_dec, b_dec, out);
}